// round 1
// baseline (speedup 1.0000x reference)
#include <cuda_runtime.h>
#include <math.h>

#define BB 4
#define SS 4096
#define DD 256
#define D2 512

// ---- scratch (static __device__ globals; no allocation anywhere) ----
__device__ float g_qk[(size_t)BB * SS * D2];        // [B*S, 512]: q | k   (32 MB)
__device__ float g_logits[(size_t)BB * SS * SS];    // [B, S, S]           (268 MB)
__device__ float g_m[BB * SS];                      // per-row max
__device__ float g_z[BB * SS];                      // per-row sum-exp
__device__ float g_w[BB * SS];                      // column weights w_k

// ---------------------------------------------------------------------------
// zero: clear g_w and d_out each replay
// ---------------------------------------------------------------------------
__global__ void zero_kernel(float* out, int n_out) {
    int i = blockIdx.x * blockDim.x + threadIdx.x;
    if (i < BB * SS) g_w[i] = 0.0f;
    if (i < n_out)   out[i] = 0.0f;
}

// ---------------------------------------------------------------------------
// NT SGEMM: C[M,N] = alpha * A(M x K, lda) * B(N x K, ldb)^T + bias[n]
// 128x128 block tile, BK=16, 256 threads, 8x8 per-thread microtile.
// All dims divide the tile sizes exactly for this problem -> no bounds checks.
// ---------------------------------------------------------------------------
__global__ __launch_bounds__(256) void sgemm_nt(
    const float* __restrict__ A, const float* __restrict__ B,
    float* __restrict__ C,
    int K, int lda, int ldb, int ldc,
    size_t sA, size_t sB, size_t sC,
    float alpha, const float* __restrict__ bias)
{
    __shared__ float As[16][128];
    __shared__ float Bs[16][128];

    const float* Ab = A + (size_t)blockIdx.z * sA + (size_t)blockIdx.y * 128 * lda;
    const float* Bb = B + (size_t)blockIdx.z * sB + (size_t)blockIdx.x * 128 * ldb;
    float*       Cb = C + (size_t)blockIdx.z * sC;

    const int tid = threadIdx.x;
    const int tx = tid & 15;        // 0..15 -> N microtile
    const int ty = tid >> 4;        // 0..15 -> M microtile
    const int lr = tid >> 2;        // 0..63  loader row
    const int lc = (tid & 3) << 2;  // 0,4,8,12 loader col (float4)

    float acc[8][8];
#pragma unroll
    for (int i = 0; i < 8; i++)
#pragma unroll
        for (int j = 0; j < 8; j++) acc[i][j] = 0.0f;

    for (int k0 = 0; k0 < K; k0 += 16) {
        float4 a0 = *reinterpret_cast<const float4*>(Ab + (size_t)lr        * lda + k0 + lc);
        float4 a1 = *reinterpret_cast<const float4*>(Ab + (size_t)(lr + 64) * lda + k0 + lc);
        float4 b0 = *reinterpret_cast<const float4*>(Bb + (size_t)lr        * ldb + k0 + lc);
        float4 b1 = *reinterpret_cast<const float4*>(Bb + (size_t)(lr + 64) * ldb + k0 + lc);

        __syncthreads();   // previous iteration's smem reads must finish
        As[lc + 0][lr] = a0.x; As[lc + 1][lr] = a0.y; As[lc + 2][lr] = a0.z; As[lc + 3][lr] = a0.w;
        As[lc + 0][lr + 64] = a1.x; As[lc + 1][lr + 64] = a1.y; As[lc + 2][lr + 64] = a1.z; As[lc + 3][lr + 64] = a1.w;
        Bs[lc + 0][lr] = b0.x; Bs[lc + 1][lr] = b0.y; Bs[lc + 2][lr] = b0.z; Bs[lc + 3][lr] = b0.w;
        Bs[lc + 0][lr + 64] = b1.x; Bs[lc + 1][lr + 64] = b1.y; Bs[lc + 2][lr + 64] = b1.z; Bs[lc + 3][lr + 64] = b1.w;
        __syncthreads();

#pragma unroll
        for (int kk = 0; kk < 16; kk++) {
            float4 ra0 = *reinterpret_cast<const float4*>(&As[kk][ty * 8]);
            float4 ra1 = *reinterpret_cast<const float4*>(&As[kk][ty * 8 + 4]);
            float4 rb0 = *reinterpret_cast<const float4*>(&Bs[kk][tx * 8]);
            float4 rb1 = *reinterpret_cast<const float4*>(&Bs[kk][tx * 8 + 4]);
            float ra[8] = {ra0.x, ra0.y, ra0.z, ra0.w, ra1.x, ra1.y, ra1.z, ra1.w};
            float rb[8] = {rb0.x, rb0.y, rb0.z, rb0.w, rb1.x, rb1.y, rb1.z, rb1.w};
#pragma unroll
            for (int i = 0; i < 8; i++)
#pragma unroll
                for (int j = 0; j < 8; j++)
                    acc[i][j] = fmaf(ra[i], rb[j], acc[i][j]);
        }
    }

#pragma unroll
    for (int i = 0; i < 8; i++) {
        size_t row = (size_t)blockIdx.y * 128 + ty * 8 + i;
#pragma unroll
        for (int j4 = 0; j4 < 8; j4 += 4) {
            int col = blockIdx.x * 128 + tx * 8 + j4;
            float4 v;
            v.x = alpha * acc[i][j4 + 0];
            v.y = alpha * acc[i][j4 + 1];
            v.z = alpha * acc[i][j4 + 2];
            v.w = alpha * acc[i][j4 + 3];
            if (bias) {
                v.x += bias[col + 0]; v.y += bias[col + 1];
                v.z += bias[col + 2]; v.w += bias[col + 3];
            }
            *reinterpret_cast<float4*>(Cb + row * ldc + col) = v;
        }
    }
}

// ---------------------------------------------------------------------------
// Row stats: per logits row, max and sum-exp. One block (256 thr) per row.
// ---------------------------------------------------------------------------
__global__ void row_stats_kernel() {
    __shared__ float red[256];
    const int row = blockIdx.x;
    const int tid = threadIdx.x;
    const float* lp = g_logits + (size_t)row * SS;

    float m = -1e30f;
    for (int j = tid; j < SS; j += 256) m = fmaxf(m, lp[j]);
    red[tid] = m;
    __syncthreads();
    for (int s = 128; s > 0; s >>= 1) {
        if (tid < s) red[tid] = fmaxf(red[tid], red[tid + s]);
        __syncthreads();
    }
    m = red[0];
    __syncthreads();

    float z = 0.0f;
    for (int j = tid; j < SS; j += 256) z += __expf(lp[j] - m);
    red[tid] = z;
    __syncthreads();
    for (int s = 128; s > 0; s >>= 1) {
        if (tid < s) red[tid] += red[tid + s];
        __syncthreads();
    }
    if (tid == 0) { g_m[row] = m; g_z[row] = red[0]; }
}

// ---------------------------------------------------------------------------
// Column weights: w[b,k] += sum over rows of exp(l - m)/z.
// Each block handles 32 consecutive rows of one batch (S%32==0 so no crossing).
// ---------------------------------------------------------------------------
__global__ void col_weights_kernel() {
    __shared__ float ws[SS];   // 16 KB partial column sums
    const int tid = threadIdx.x;
    const int r0 = blockIdx.x * 32;
    const int b = r0 / SS;

    for (int j = tid; j < SS; j += 256) ws[j] = 0.0f;
    __syncthreads();

    for (int r = r0; r < r0 + 32; r++) {
        const float m = g_m[r];
        const float iz = 1.0f / g_z[r];
        const float* lp = g_logits + (size_t)r * SS;
        for (int j = tid; j < SS; j += 256)
            ws[j] += __expf(lp[j] - m) * iz;     // each j owned by one thread
    }
    __syncthreads();

    float* wb = g_w + (size_t)b * SS;
    for (int j = tid; j < SS; j += 256) atomicAdd(&wb[j], ws[j]);
}

// ---------------------------------------------------------------------------
// Weighted pool: out[b,d] = sum_k w[b,k] * x[b,k,d]. 64 keys per block.
// ---------------------------------------------------------------------------
__global__ void out_kernel(const float* __restrict__ x, float* __restrict__ out) {
    const int b = blockIdx.y;
    const int k0 = blockIdx.x * 64;
    const int d = threadIdx.x;   // 256 threads = one per head dim

    const float* xp = x + ((size_t)b * SS + k0) * DD + d;
    const float* wp = g_w + (size_t)b * SS + k0;
    float acc = 0.0f;
#pragma unroll 8
    for (int kk = 0; kk < 64; kk++)
        acc = fmaf(wp[kk], xp[(size_t)kk * DD], acc);
    atomicAdd(&out[b * DD + d], acc);
}

// ---------------------------------------------------------------------------
extern "C" void kernel_launch(void* const* d_in, const int* in_sizes, int n_in,
                              void* d_out, int out_size) {
    const float* x    = (const float*)d_in[0];   // [B,S,D]
    const float* W    = (const float*)d_in[1];   // [2D,D]
    const float* bias = (const float*)d_in[2];   // [2D]
    float* out = (float*)d_out;                  // [B,D]

    float *p_qk = nullptr, *p_logits = nullptr;
    cudaGetSymbolAddress((void**)&p_qk, g_qk);
    cudaGetSymbolAddress((void**)&p_logits, g_logits);

    // 0) zero accumulators
    zero_kernel<<<64, 256>>>(out, out_size);

    // 1) projection: qk[B*S,512] = x[B*S,256] @ W[512,256]^T + bias
    {
        dim3 grid(D2 / 128, (BB * SS) / 128, 1);
        sgemm_nt<<<grid, 256>>>(x, W, p_qk,
                                DD, DD, DD, D2,
                                0, 0, 0,
                                1.0f, bias);
    }

    // 2) logits[b] = (1/16) * Q[b] @ K[b]^T   (Q = qk cols 0:256, K = cols 256:512)
    {
        dim3 grid(SS / 128, SS / 128, BB);
        sgemm_nt<<<grid, 256>>>(p_qk, p_qk + DD, p_logits,
                                DD, D2, D2, SS,
                                (size_t)SS * D2, (size_t)SS * D2, (size_t)SS * SS,
                                0.0625f, nullptr);
    }

    // 3) softmax row stats
    row_stats_kernel<<<BB * SS, 256>>>();

    // 4) column weights w_k = sum_q attn[q,k]
    col_weights_kernel<<<(BB * SS) / 32, 256>>>();

    // 5) out[b,d] = sum_k w[b,k] * x[b,k,d]
    out_kernel<<<dim3(64, BB), 256>>>(x, out);
}

// round 3
// speedup vs baseline: 2.1249x; 2.1249x over previous
#include <cuda_runtime.h>
#include <cuda_bf16.h>
#include <cstdint>
#include <math.h>

#define BB 4
#define SS 4096
#define DD 256
#define D2 512

// ---- scratch (static __device__ globals; no allocation anywhere) ----
__device__ __nv_bfloat16 g_qh[(size_t)BB * SS * DD];   // q hi  (8 MB)
__device__ __nv_bfloat16 g_ql[(size_t)BB * SS * DD];   // q lo
__device__ __nv_bfloat16 g_kh[(size_t)BB * SS * DD];   // k hi
__device__ __nv_bfloat16 g_kl[(size_t)BB * SS * DD];   // k lo
__device__ __nv_bfloat16 g_P[(size_t)BB * SS * SS];    // exp(logits) bf16 (134 MB)
__device__ float         g_z[BB * SS];                 // per-row sum-exp
__device__ float         g_w[BB * SS];                 // column weights

// ===========================================================================
// helpers
// ===========================================================================
__device__ __forceinline__ uint32_t smem_u32(const void* p) {
    uint32_t a;
    asm("{ .reg .u64 t; cvta.to.shared.u64 t, %1; cvt.u32.u64 %0, t; }" : "=r"(a) : "l"(p));
    return a;
}
__device__ __forceinline__ void ldmx4(uint32_t* r, uint32_t addr) {
    asm volatile("ldmatrix.sync.aligned.m8n8.x4.shared.b16 {%0,%1,%2,%3}, [%4];"
                 : "=r"(r[0]), "=r"(r[1]), "=r"(r[2]), "=r"(r[3]) : "r"(addr));
}
__device__ __forceinline__ void ldmx2(uint32_t* r, uint32_t addr) {
    asm volatile("ldmatrix.sync.aligned.m8n8.x2.shared.b16 {%0,%1}, [%2];"
                 : "=r"(r[0]), "=r"(r[1]) : "r"(addr));
}
__device__ __forceinline__ void mma16816(float* c, const uint32_t* a, const uint32_t* b) {
    asm volatile(
        "mma.sync.aligned.m16n8k16.row.col.f32.bf16.bf16.f32 "
        "{%0,%1,%2,%3}, {%4,%5,%6,%7}, {%8,%9}, {%0,%1,%2,%3};"
        : "+f"(c[0]), "+f"(c[1]), "+f"(c[2]), "+f"(c[3])
        : "r"(a[0]), "r"(a[1]), "r"(a[2]), "r"(a[3]), "r"(b[0]), "r"(b[1]));
}

// ===========================================================================
// zero: clear accumulators each replay
// ===========================================================================
__global__ void zero_kernel(float* out, int n_out) {
    int i = blockIdx.x * blockDim.x + threadIdx.x;
    if (i < BB * SS) { g_w[i] = 0.0f; g_z[i] = 0.0f; }
    if (i < n_out)   out[i] = 0.0f;
}

// ===========================================================================
// fp32 projection SGEMM: qk = x @ W^T + bias, epilogue splits to hi/lo bf16.
// A = x [B*S, 256], B = W [512, 256]; tile 128x128, BK=16, 256 thr, 8x8 micro.
// ===========================================================================
__global__ __launch_bounds__(256) void proj_kernel(
    const float* __restrict__ A, const float* __restrict__ B,
    const float* __restrict__ bias)
{
    __shared__ float As[16][128];
    __shared__ float Bs[16][128];

    const float* Ab = A + (size_t)blockIdx.y * 128 * DD;
    const float* Bb = B + (size_t)blockIdx.x * 128 * DD;

    const int tid = threadIdx.x;
    const int tx = tid & 15, ty = tid >> 4;
    const int lr = tid >> 2, lc = (tid & 3) << 2;

    float acc[8][8];
#pragma unroll
    for (int i = 0; i < 8; i++)
#pragma unroll
        for (int j = 0; j < 8; j++) acc[i][j] = 0.0f;

    for (int k0 = 0; k0 < DD; k0 += 16) {
        float4 a0 = *reinterpret_cast<const float4*>(Ab + (size_t)lr * DD + k0 + lc);
        float4 a1 = *reinterpret_cast<const float4*>(Ab + (size_t)(lr + 64) * DD + k0 + lc);
        float4 b0 = *reinterpret_cast<const float4*>(Bb + (size_t)lr * DD + k0 + lc);
        float4 b1 = *reinterpret_cast<const float4*>(Bb + (size_t)(lr + 64) * DD + k0 + lc);
        __syncthreads();
        As[lc + 0][lr] = a0.x; As[lc + 1][lr] = a0.y; As[lc + 2][lr] = a0.z; As[lc + 3][lr] = a0.w;
        As[lc + 0][lr + 64] = a1.x; As[lc + 1][lr + 64] = a1.y; As[lc + 2][lr + 64] = a1.z; As[lc + 3][lr + 64] = a1.w;
        Bs[lc + 0][lr] = b0.x; Bs[lc + 1][lr] = b0.y; Bs[lc + 2][lr] = b0.z; Bs[lc + 3][lr] = b0.w;
        Bs[lc + 0][lr + 64] = b1.x; Bs[lc + 1][lr + 64] = b1.y; Bs[lc + 2][lr + 64] = b1.z; Bs[lc + 3][lr + 64] = b1.w;
        __syncthreads();
#pragma unroll
        for (int kk = 0; kk < 16; kk++) {
            float4 ra0 = *reinterpret_cast<const float4*>(&As[kk][ty * 8]);
            float4 ra1 = *reinterpret_cast<const float4*>(&As[kk][ty * 8 + 4]);
            float4 rb0 = *reinterpret_cast<const float4*>(&Bs[kk][tx * 8]);
            float4 rb1 = *reinterpret_cast<const float4*>(&Bs[kk][tx * 8 + 4]);
            float ra[8] = {ra0.x, ra0.y, ra0.z, ra0.w, ra1.x, ra1.y, ra1.z, ra1.w};
            float rb[8] = {rb0.x, rb0.y, rb0.z, rb0.w, rb1.x, rb1.y, rb1.z, rb1.w};
#pragma unroll
            for (int i = 0; i < 8; i++)
#pragma unroll
                for (int j = 0; j < 8; j++)
                    acc[i][j] = fmaf(ra[i], rb[j], acc[i][j]);
        }
    }

#pragma unroll
    for (int i = 0; i < 8; i++) {
        size_t row = (size_t)blockIdx.y * 128 + ty * 8 + i;
#pragma unroll
        for (int j4 = 0; j4 < 8; j4 += 4) {
            int col = blockIdx.x * 128 + tx * 8 + j4;
            float v[4];
#pragma unroll
            for (int u = 0; u < 4; u++) v[u] = acc[i][j4 + u] + bias[col + u];

            const bool isq = (col < DD);
            const int c0 = isq ? col : col - DD;
            __nv_bfloat16* dh = (isq ? g_qh : g_kh) + row * DD + c0;
            __nv_bfloat16* dl = (isq ? g_ql : g_kl) + row * DD + c0;

            __nv_bfloat16 h[4], l[4];
#pragma unroll
            for (int u = 0; u < 4; u++) {
                h[u] = __float2bfloat16_rn(v[u]);
                l[u] = __float2bfloat16_rn(v[u] - __bfloat162float(h[u]));
            }
            uint2 ph, pl;
            ph.x = (uint32_t)__bfloat16_as_ushort(h[0]) | ((uint32_t)__bfloat16_as_ushort(h[1]) << 16);
            ph.y = (uint32_t)__bfloat16_as_ushort(h[2]) | ((uint32_t)__bfloat16_as_ushort(h[3]) << 16);
            pl.x = (uint32_t)__bfloat16_as_ushort(l[0]) | ((uint32_t)__bfloat16_as_ushort(l[1]) << 16);
            pl.y = (uint32_t)__bfloat16_as_ushort(l[2]) | ((uint32_t)__bfloat16_as_ushort(l[3]) << 16);
            *reinterpret_cast<uint2*>(dh) = ph;
            *reinterpret_cast<uint2*>(dl) = pl;
        }
    }
}

// ===========================================================================
// logits kernel: CTA = 128(q) x 128(k) tile, K=256, mma.sync bf16 3-term split.
// 8 warps in 2(m) x 4(n); each warp 64x32. Fused epilogue: P=exp(l/16) bf16,
// row sums into g_z.
// SMEM rows padded to 80B -> conflict-free ldmatrix (stride 20 words).
// ===========================================================================
#define PADB 80
__global__ __launch_bounds__(256, 2) void logits_kernel() {
    __shared__ __align__(16) char tiles[4 * 128 * PADB];   // Ah|Al|Bh|Bl, 40 KB
    __shared__ float zrow[128];

    const int tid = threadIdx.x;
    const int lane = tid & 31, wid = tid >> 5;
    const int wm = wid >> 2, wn = wid & 3;
    const int nt = blockIdx.x, qt = blockIdx.y, b = blockIdx.z;

    if (tid < 128) zrow[tid] = 0.0f;

    const uint32_t sb = smem_u32(tiles);

    const size_t qrow0 = ((size_t)b * SS + (size_t)qt * 128) * DD;
    const size_t krow0 = ((size_t)b * SS + (size_t)nt * 128) * DD;
    const __nv_bfloat16* srcs[4] = { g_qh + qrow0, g_ql + qrow0,
                                     g_kh + krow0, g_kl + krow0 };

    float acc[4][4][4];
#pragma unroll
    for (int m = 0; m < 4; m++)
#pragma unroll
        for (int n = 0; n < 4; n++)
#pragma unroll
            for (int u = 0; u < 4; u++) acc[m][n][u] = 0.0f;

    // ldmatrix lane->address components
    const uint32_t a_row = (uint32_t)(lane & 15);
    const uint32_t a_koff = (uint32_t)((lane >> 4) << 4);       // 0 / 16 B
    const uint32_t b_row = (uint32_t)(lane & 7);
    const uint32_t b_koff = (uint32_t)(((lane >> 3) & 1) << 4); // 0 / 16 B

    for (int kt = 0; kt < 8; kt++) {           // BK = 32
        __syncthreads();
#pragma unroll
        for (int arr = 0; arr < 4; arr++) {
            const __nv_bfloat16* s = srcs[arr];
#pragma unroll
            for (int i = 0; i < 2; i++) {
                int chunk = tid + i * 256;     // 512 chunks of 8 bf16
                int row = chunk >> 2, c4 = chunk & 3;
                uint4 v = *reinterpret_cast<const uint4*>(s + (size_t)row * DD + kt * 32 + c4 * 8);
                *reinterpret_cast<uint4*>(tiles + arr * 10240 + row * PADB + c4 * 16) = v;
            }
        }
        __syncthreads();

#pragma unroll
        for (int k16 = 0; k16 < 2; k16++) {
            const uint32_t kb = (uint32_t)(k16 * 32);
            uint32_t bh[4][2], bl[4][2];
#pragma unroll
            for (int n = 0; n < 4; n++) {
                uint32_t boff = (uint32_t)(wn * 32 + n * 8 + b_row) * PADB + kb + b_koff;
                ldmx2(bh[n], sb + 20480 + boff);
                ldmx2(bl[n], sb + 30720 + boff);
            }
#pragma unroll
            for (int m = 0; m < 4; m++) {
                uint32_t aoff = (uint32_t)(wm * 64 + m * 16 + a_row) * PADB + kb + a_koff;
                uint32_t ah[4], al[4];
                ldmx4(ah, sb + aoff);
                ldmx4(al, sb + 10240 + aoff);
#pragma unroll
                for (int n = 0; n < 4; n++) {
                    mma16816(acc[m][n], ah, bh[n]);
                    mma16816(acc[m][n], ah, bl[n]);
                    mma16816(acc[m][n], al, bh[n]);
                }
            }
        }
    }
    __syncthreads();

    // ---- fused epilogue: exp, bf16 store, row sums ----
    const int g = lane >> 2, t2 = (lane & 3) * 2;
#pragma unroll
    for (int m = 0; m < 4; m++) {
        const int row_lo = wm * 64 + m * 16 + g;
        const size_t grow = (size_t)b * SS + (size_t)qt * 128 + row_lo;
        float zlo = 0.0f, zhi = 0.0f;
#pragma unroll
        for (int n = 0; n < 4; n++) {
            float e0 = __expf(acc[m][n][0] * 0.0625f);
            float e1 = __expf(acc[m][n][1] * 0.0625f);
            float e2 = __expf(acc[m][n][2] * 0.0625f);
            float e3 = __expf(acc[m][n][3] * 0.0625f);
            zlo += e0 + e1;
            zhi += e2 + e3;
            uint32_t p01 = (uint32_t)__bfloat16_as_ushort(__float2bfloat16_rn(e0))
                         | ((uint32_t)__bfloat16_as_ushort(__float2bfloat16_rn(e1)) << 16);
            uint32_t p23 = (uint32_t)__bfloat16_as_ushort(__float2bfloat16_rn(e2))
                         | ((uint32_t)__bfloat16_as_ushort(__float2bfloat16_rn(e3)) << 16);
            const int col = nt * 128 + wn * 32 + n * 8 + t2;
            *reinterpret_cast<uint32_t*>(g_P + grow * SS + col) = p01;
            *reinterpret_cast<uint32_t*>(g_P + (grow + 8) * SS + col) = p23;
        }
        atomicAdd(&zrow[row_lo], zlo);
        atomicAdd(&zrow[row_lo + 8], zhi);
    }
    __syncthreads();
    if (tid < 128)
        atomicAdd(&g_z[(size_t)b * SS + (size_t)qt * 128 + tid], zrow[tid]);
}

// ===========================================================================
// column weights: w_k += sum_q P[q,k] / z_q.  Block owns 32 q-rows.
// ws transposed layout ws[i*512 + j] holds column j*8+i  (conflict-free).
// ===========================================================================
__global__ __launch_bounds__(256) void col_weights_kernel() {
    __shared__ float ws[SS];   // 16 KB
    const int tid = threadIdx.x;
    const int r0 = blockIdx.x * 32;
    const int b = r0 / SS;

    for (int j = tid; j < SS; j += 256) ws[j] = 0.0f;
    __syncthreads();

    for (int r = r0; r < r0 + 32; r++) {
        const float iz = 1.0f / g_z[r];
        const uint4* lp = reinterpret_cast<const uint4*>(g_P + (size_t)r * SS);
        for (int j = tid; j < SS / 8; j += 256) {
            uint4 v = lp[j];
            const uint32_t wv[4] = {v.x, v.y, v.z, v.w};
#pragma unroll
            for (int h = 0; h < 4; h++) {
                float f0 = __bfloat162float(__ushort_as_bfloat16((unsigned short)(wv[h] & 0xFFFF)));
                float f1 = __bfloat162float(__ushort_as_bfloat16((unsigned short)(wv[h] >> 16)));
                ws[(2 * h + 0) * 512 + j] += f0 * iz;
                ws[(2 * h + 1) * 512 + j] += f1 * iz;
            }
        }
    }
    __syncthreads();

    float* wb = g_w + (size_t)b * SS;
#pragma unroll
    for (int h = 0; h < 8; h++)
        for (int j = tid; j < 512; j += 256)
            atomicAdd(&wb[j * 8 + h], ws[h * 512 + j]);
}

// ===========================================================================
// weighted pool: out[b,d] = sum_k w[b,k] * x[b,k,d]
// ===========================================================================
__global__ void out_kernel(const float* __restrict__ x, float* __restrict__ out) {
    const int b = blockIdx.y;
    const int k0 = blockIdx.x * 64;
    const int d = threadIdx.x;

    const float* xp = x + ((size_t)b * SS + k0) * DD + d;
    const float* wp = g_w + (size_t)b * SS + k0;
    float acc = 0.0f;
#pragma unroll 8
    for (int kk = 0; kk < 64; kk++)
        acc = fmaf(wp[kk], xp[(size_t)kk * DD], acc);
    atomicAdd(&out[b * DD + d], acc);
}

// ===========================================================================
extern "C" void kernel_launch(void* const* d_in, const int* in_sizes, int n_in,
                              void* d_out, int out_size) {
    const float* x    = (const float*)d_in[0];
    const float* W    = (const float*)d_in[1];
    const float* bias = (const float*)d_in[2];
    float* out = (float*)d_out;

    // 0) zero accumulators
    zero_kernel<<<64, 256>>>(out, out_size);

    // 1) projection + hi/lo bf16 split
    {
        dim3 grid(D2 / 128, (BB * SS) / 128);
        proj_kernel<<<grid, 256>>>(x, W, bias);
    }

    // 2) logits + exp + z  (mma.sync bf16, 3-term split)
    {
        dim3 grid(SS / 128, SS / 128, BB);
        logits_kernel<<<grid, 256>>>();
    }

    // 3) column weights
    col_weights_kernel<<<(BB * SS) / 32, 256>>>();

    // 4) weighted pool
    out_kernel<<<dim3(64, BB), 256>>>(x, out);
}

// round 4
// speedup vs baseline: 3.5978x; 1.6932x over previous
#include <cuda_runtime.h>
#include <cuda_bf16.h>
#include <cstdint>
#include <math.h>

#define BB 4
#define SS 4096
#define DD 256
#define D2 512

// ---- scratch (static __device__ globals; no allocation anywhere) ----
__device__ __nv_bfloat16 g_q[(size_t)BB * SS * DD];    // q bf16 (8 MB)
__device__ __nv_bfloat16 g_k[(size_t)BB * SS * DD];    // k bf16 (8 MB)
__device__ __nv_bfloat16 g_P[(size_t)BB * SS * SS];    // exp(logits) bf16 (134 MB)
__device__ float         g_z[BB * SS];                 // per-row sum-exp
__device__ float         g_w[BB * SS];                 // column weights

// ===========================================================================
// helpers
// ===========================================================================
__device__ __forceinline__ uint32_t smem_u32(const void* p) {
    uint32_t a;
    asm("{ .reg .u64 t; cvta.to.shared.u64 t, %1; cvt.u32.u64 %0, t; }" : "=r"(a) : "l"(p));
    return a;
}
__device__ __forceinline__ void ldmx4(uint32_t* r, uint32_t addr) {
    asm volatile("ldmatrix.sync.aligned.m8n8.x4.shared.b16 {%0,%1,%2,%3}, [%4];"
                 : "=r"(r[0]), "=r"(r[1]), "=r"(r[2]), "=r"(r[3]) : "r"(addr));
}
__device__ __forceinline__ void ldmx2(uint32_t* r, uint32_t addr) {
    asm volatile("ldmatrix.sync.aligned.m8n8.x2.shared.b16 {%0,%1}, [%2];"
                 : "=r"(r[0]), "=r"(r[1]) : "r"(addr));
}
__device__ __forceinline__ void mma16816(float* c, const uint32_t* a, const uint32_t* b) {
    asm volatile(
        "mma.sync.aligned.m16n8k16.row.col.f32.bf16.bf16.f32 "
        "{%0,%1,%2,%3}, {%4,%5,%6,%7}, {%8,%9}, {%0,%1,%2,%3};"
        : "+f"(c[0]), "+f"(c[1]), "+f"(c[2]), "+f"(c[3])
        : "r"(a[0]), "r"(a[1]), "r"(a[2]), "r"(a[3]), "r"(b[0]), "r"(b[1]));
}
__device__ __forceinline__ uint32_t pack_bf16(float x, float y) {
    return (uint32_t)__bfloat16_as_ushort(__float2bfloat16_rn(x))
         | ((uint32_t)__bfloat16_as_ushort(__float2bfloat16_rn(y)) << 16);
}

#define PADB 80   // bytes per smem tile row (64B data + 16B pad, conflict-free)

// ===========================================================================
// zero: clear accumulators each replay
// ===========================================================================
__global__ void zero_kernel(float* out, int n_out) {
    int i = blockIdx.x * blockDim.x + threadIdx.x;
    if (i < BB * SS) { g_w[i] = 0.0f; g_z[i] = 0.0f; }
    if (i < n_out)   out[i] = 0.0f;
}

// ===========================================================================
// projection: qk[B*S,512] = x @ W^T + bias, split-bf16 3-term HMMA
// (fp32-accurate). Epilogue stores bf16 q / k directly.
// CTA = 128(rows) x 128(cols), 8 warps 2x4, warp tile 64x32, BK=32.
// SMEM: Ah | Al | Bh | Bl, each 128 rows x 32 bf16 (PADB stride) = 40 KB.
// ===========================================================================
__global__ __launch_bounds__(256, 2) void proj_kernel(
    const float* __restrict__ x, const float* __restrict__ W,
    const float* __restrict__ bias)
{
    __shared__ __align__(16) char tiles[4 * 128 * PADB];

    const int tid = threadIdx.x;
    const int lane = tid & 31, wid = tid >> 5;
    const int wm = wid >> 2, wn = wid & 3;

    const float* Ab = x + (size_t)blockIdx.y * 128 * DD;
    const float* Bb = W + (size_t)blockIdx.x * 128 * DD;
    const uint32_t sb = smem_u32(tiles);

    float acc[4][4][4];
#pragma unroll
    for (int m = 0; m < 4; m++)
#pragma unroll
        for (int n = 0; n < 4; n++)
#pragma unroll
            for (int u = 0; u < 4; u++) acc[m][n][u] = 0.0f;

    const uint32_t a_row = (uint32_t)(lane & 15);
    const uint32_t a_koff = (uint32_t)((lane >> 4) << 4);
    const uint32_t b_row = (uint32_t)(lane & 7);
    const uint32_t b_koff = (uint32_t)(((lane >> 3) & 1) << 4);

    for (int kt = 0; kt < 8; kt++) {       // K = 256, BK = 32
        __syncthreads();
#pragma unroll
        for (int half = 0; half < 2; half++) {
            const float* src = half ? Bb : Ab;
            char* dh = tiles + (half ? 2 : 0) * 10240;
            char* dl = dh + 10240;
#pragma unroll
            for (int i = 0; i < 4; i++) {
                int chunk = tid + i * 256;           // 1024 chunks of 4 floats
                int row = chunk >> 3, c4 = chunk & 7;
                float4 v = *reinterpret_cast<const float4*>(src + (size_t)row * DD + kt * 32 + c4 * 4);
                float hx = __bfloat162float(__float2bfloat16_rn(v.x));
                float hy = __bfloat162float(__float2bfloat16_rn(v.y));
                float hz = __bfloat162float(__float2bfloat16_rn(v.z));
                float hw = __bfloat162float(__float2bfloat16_rn(v.w));
                uint2 ph, pl;
                ph.x = pack_bf16(v.x, v.y); ph.y = pack_bf16(v.z, v.w);
                pl.x = pack_bf16(v.x - hx, v.y - hy); pl.y = pack_bf16(v.z - hz, v.w - hw);
                *reinterpret_cast<uint2*>(dh + row * PADB + c4 * 8) = ph;
                *reinterpret_cast<uint2*>(dl + row * PADB + c4 * 8) = pl;
            }
        }
        __syncthreads();

#pragma unroll
        for (int k16 = 0; k16 < 2; k16++) {
            const uint32_t kb = (uint32_t)(k16 * 32);
            uint32_t bh[4][2], bl[4][2];
#pragma unroll
            for (int n = 0; n < 4; n++) {
                uint32_t boff = (uint32_t)(wn * 32 + n * 8 + b_row) * PADB + kb + b_koff;
                ldmx2(bh[n], sb + 20480 + boff);
                ldmx2(bl[n], sb + 30720 + boff);
            }
#pragma unroll
            for (int m = 0; m < 4; m++) {
                uint32_t aoff = (uint32_t)(wm * 64 + m * 16 + a_row) * PADB + kb + a_koff;
                uint32_t ah[4], al[4];
                ldmx4(ah, sb + aoff);
                ldmx4(al, sb + 10240 + aoff);
#pragma unroll
                for (int n = 0; n < 4; n++) {
                    mma16816(acc[m][n], ah, bh[n]);
                    mma16816(acc[m][n], ah, bl[n]);
                    mma16816(acc[m][n], al, bh[n]);
                }
            }
        }
    }

    // ---- epilogue: + bias, bf16 store to g_q / g_k ----
    const int g = lane >> 2, t2 = (lane & 3) * 2;
#pragma unroll
    for (int m = 0; m < 4; m++) {
        const size_t grow = (size_t)blockIdx.y * 128 + wm * 64 + m * 16 + g;
#pragma unroll
        for (int n = 0; n < 4; n++) {
            const int col = blockIdx.x * 128 + wn * 32 + n * 8 + t2;
            const float b0 = bias[col], b1 = bias[col + 1];
            uint32_t p01 = pack_bf16(acc[m][n][0] + b0, acc[m][n][1] + b1);
            uint32_t p23 = pack_bf16(acc[m][n][2] + b0, acc[m][n][3] + b1);
            __nv_bfloat16* base = (col < DD) ? (g_q + (size_t)0 + col)
                                             : (g_k + (size_t)0 + (col - DD));
            *reinterpret_cast<uint32_t*>(base + grow * DD)       = p01;
            *reinterpret_cast<uint32_t*>(base + (grow + 8) * DD) = p23;
        }
    }
}

// ===========================================================================
// logits kernel: CTA = 128(q) x 128(k), K=256, single bf16 HMMA.
// Fused epilogue: P = exp(logits/16) bf16 + row sums into g_z.
// SMEM: Ah | Bh, each 128 x 32 bf16 (PADB stride) = 20 KB.
// ===========================================================================
__global__ __launch_bounds__(256, 2) void logits_kernel() {
    __shared__ __align__(16) char tiles[2 * 128 * PADB];
    __shared__ float zrow[128];

    const int tid = threadIdx.x;
    const int lane = tid & 31, wid = tid >> 5;
    const int wm = wid >> 2, wn = wid & 3;
    const int nt = blockIdx.x, qt = blockIdx.y, b = blockIdx.z;

    if (tid < 128) zrow[tid] = 0.0f;

    const uint32_t sb = smem_u32(tiles);
    const __nv_bfloat16* Qs = g_q + ((size_t)b * SS + (size_t)qt * 128) * DD;
    const __nv_bfloat16* Ks = g_k + ((size_t)b * SS + (size_t)nt * 128) * DD;

    float acc[4][4][4];
#pragma unroll
    for (int m = 0; m < 4; m++)
#pragma unroll
        for (int n = 0; n < 4; n++)
#pragma unroll
            for (int u = 0; u < 4; u++) acc[m][n][u] = 0.0f;

    const uint32_t a_row = (uint32_t)(lane & 15);
    const uint32_t a_koff = (uint32_t)((lane >> 4) << 4);
    const uint32_t b_row = (uint32_t)(lane & 7);
    const uint32_t b_koff = (uint32_t)(((lane >> 3) & 1) << 4);

    for (int kt = 0; kt < 8; kt++) {       // BK = 32
        __syncthreads();
#pragma unroll
        for (int half = 0; half < 2; half++) {
            const __nv_bfloat16* s = half ? Ks : Qs;
            char* dst = tiles + half * 10240;
#pragma unroll
            for (int i = 0; i < 2; i++) {
                int chunk = tid + i * 256;          // 512 chunks of 8 bf16
                int row = chunk >> 2, c4 = chunk & 3;
                uint4 v = *reinterpret_cast<const uint4*>(s + (size_t)row * DD + kt * 32 + c4 * 8);
                *reinterpret_cast<uint4*>(dst + row * PADB + c4 * 16) = v;
            }
        }
        __syncthreads();

#pragma unroll
        for (int k16 = 0; k16 < 2; k16++) {
            const uint32_t kb = (uint32_t)(k16 * 32);
            uint32_t bh[4][2];
#pragma unroll
            for (int n = 0; n < 4; n++) {
                uint32_t boff = (uint32_t)(wn * 32 + n * 8 + b_row) * PADB + kb + b_koff;
                ldmx2(bh[n], sb + 10240 + boff);
            }
#pragma unroll
            for (int m = 0; m < 4; m++) {
                uint32_t aoff = (uint32_t)(wm * 64 + m * 16 + a_row) * PADB + kb + a_koff;
                uint32_t ah[4];
                ldmx4(ah, sb + aoff);
#pragma unroll
                for (int n = 0; n < 4; n++)
                    mma16816(acc[m][n], ah, bh[n]);
            }
        }
    }
    __syncthreads();

    // ---- fused epilogue: exp, bf16 store, row sums ----
    const int g = lane >> 2, t2 = (lane & 3) * 2;
#pragma unroll
    for (int m = 0; m < 4; m++) {
        const int row_lo = wm * 64 + m * 16 + g;
        const size_t grow = (size_t)b * SS + (size_t)qt * 128 + row_lo;
        float zlo = 0.0f, zhi = 0.0f;
#pragma unroll
        for (int n = 0; n < 4; n++) {
            float e0 = __expf(acc[m][n][0] * 0.0625f);
            float e1 = __expf(acc[m][n][1] * 0.0625f);
            float e2 = __expf(acc[m][n][2] * 0.0625f);
            float e3 = __expf(acc[m][n][3] * 0.0625f);
            zlo += e0 + e1;
            zhi += e2 + e3;
            const int col = nt * 128 + wn * 32 + n * 8 + t2;
            *reinterpret_cast<uint32_t*>(g_P + grow * SS + col)       = pack_bf16(e0, e1);
            *reinterpret_cast<uint32_t*>(g_P + (grow + 8) * SS + col) = pack_bf16(e2, e3);
        }
        atomicAdd(&zrow[row_lo], zlo);
        atomicAdd(&zrow[row_lo + 8], zhi);
    }
    __syncthreads();
    if (tid < 128)
        atomicAdd(&g_z[(size_t)b * SS + (size_t)qt * 128 + tid], zrow[tid]);
}

// ===========================================================================
// column weights: w_k += sum_q P[q,k] / z_q.  Block owns 16 q-rows (1024 blks).
// ws transposed layout ws[i*512 + j] holds column j*8+i (conflict-free).
// ===========================================================================
__global__ __launch_bounds__(256) void col_weights_kernel() {
    __shared__ float ws[SS];   // 16 KB
    const int tid = threadIdx.x;
    const int r0 = blockIdx.x * 16;
    const int b = r0 / SS;

    for (int j = tid; j < SS; j += 256) ws[j] = 0.0f;
    __syncthreads();

    for (int r = r0; r < r0 + 16; r++) {
        const float iz = 1.0f / g_z[r];
        const uint4* lp = reinterpret_cast<const uint4*>(g_P + (size_t)r * SS);
        for (int j = tid; j < SS / 8; j += 256) {
            uint4 v = lp[j];
            const uint32_t wv[4] = {v.x, v.y, v.z, v.w};
#pragma unroll
            for (int h = 0; h < 4; h++) {
                float f0 = __bfloat162float(__ushort_as_bfloat16((unsigned short)(wv[h] & 0xFFFF)));
                float f1 = __bfloat162float(__ushort_as_bfloat16((unsigned short)(wv[h] >> 16)));
                ws[(2 * h + 0) * 512 + j] += f0 * iz;
                ws[(2 * h + 1) * 512 + j] += f1 * iz;
            }
        }
    }
    __syncthreads();

    float* wb = g_w + (size_t)b * SS;
#pragma unroll
    for (int h = 0; h < 8; h++)
        for (int j = tid; j < 512; j += 256)
            atomicAdd(&wb[j * 8 + h], ws[h * 512 + j]);
}

// ===========================================================================
// weighted pool: out[b,d] = sum_k w[b,k] * x[b,k,d]
// ===========================================================================
__global__ void out_kernel(const float* __restrict__ x, float* __restrict__ out) {
    const int b = blockIdx.y;
    const int k0 = blockIdx.x * 64;
    const int d = threadIdx.x;

    const float* xp = x + ((size_t)b * SS + k0) * DD + d;
    const float* wp = g_w + (size_t)b * SS + k0;
    float acc = 0.0f;
#pragma unroll 8
    for (int kk = 0; kk < 64; kk++)
        acc = fmaf(wp[kk], xp[(size_t)kk * DD], acc);
    atomicAdd(&out[b * DD + d], acc);
}

// ===========================================================================
extern "C" void kernel_launch(void* const* d_in, const int* in_sizes, int n_in,
                              void* d_out, int out_size) {
    const float* x    = (const float*)d_in[0];
    const float* W    = (const float*)d_in[1];
    const float* bias = (const float*)d_in[2];
    float* out = (float*)d_out;

    // 0) zero accumulators
    zero_kernel<<<64, 256>>>(out, out_size);

    // 1) projection (split-bf16 3-term HMMA), bf16 q/k out
    {
        dim3 grid(D2 / 128, (BB * SS) / 128);
        proj_kernel<<<grid, 256>>>(x, W, bias);
    }

    // 2) logits + exp + z  (single bf16 HMMA)
    {
        dim3 grid(SS / 128, SS / 128, BB);
        logits_kernel<<<grid, 256>>>();
    }

    // 3) column weights
    col_weights_kernel<<<(BB * SS) / 16, 256>>>();

    // 4) weighted pool
    out_kernel<<<dim3(64, BB), 256>>>(x, out);
}

// round 5
// speedup vs baseline: 4.3281x; 1.2030x over previous
#include <cuda_runtime.h>
#include <cuda_bf16.h>
#include <cstdint>
#include <math.h>

#define BB 4
#define SS 4096
#define DD 256
#define D2 512

// ---- scratch (static __device__ globals; no allocation anywhere) ----
__device__ __nv_bfloat16 g_q[(size_t)BB * SS * DD];    // q bf16 (8 MB)
__device__ __nv_bfloat16 g_k[(size_t)BB * SS * DD];    // k bf16 (8 MB)
__device__ __nv_bfloat16 g_P[(size_t)BB * SS * SS];    // exp(logits) bf16 (134 MB)
__device__ float         g_z[BB * SS];                 // per-row sum-exp
__device__ float         g_w[BB * SS];                 // column weights

// ===========================================================================
// helpers
// ===========================================================================
__device__ __forceinline__ uint32_t smem_u32(const void* p) {
    uint32_t a;
    asm("{ .reg .u64 t; cvta.to.shared.u64 t, %1; cvt.u32.u64 %0, t; }" : "=r"(a) : "l"(p));
    return a;
}
__device__ __forceinline__ void ldmx4(uint32_t* r, uint32_t addr) {
    asm volatile("ldmatrix.sync.aligned.m8n8.x4.shared.b16 {%0,%1,%2,%3}, [%4];"
                 : "=r"(r[0]), "=r"(r[1]), "=r"(r[2]), "=r"(r[3]) : "r"(addr));
}
__device__ __forceinline__ void ldmx2(uint32_t* r, uint32_t addr) {
    asm volatile("ldmatrix.sync.aligned.m8n8.x2.shared.b16 {%0,%1}, [%2];"
                 : "=r"(r[0]), "=r"(r[1]) : "r"(addr));
}
__device__ __forceinline__ void mma16816(float* c, const uint32_t* a, const uint32_t* b) {
    asm volatile(
        "mma.sync.aligned.m16n8k16.row.col.f32.bf16.bf16.f32 "
        "{%0,%1,%2,%3}, {%4,%5,%6,%7}, {%8,%9}, {%0,%1,%2,%3};"
        : "+f"(c[0]), "+f"(c[1]), "+f"(c[2]), "+f"(c[3])
        : "r"(a[0]), "r"(a[1]), "r"(a[2]), "r"(a[3]), "r"(b[0]), "r"(b[1]));
}
__device__ __forceinline__ uint32_t pack_bf16(float x, float y) {
    return (uint32_t)__bfloat16_as_ushort(__float2bfloat16_rn(x))
         | ((uint32_t)__bfloat16_as_ushort(__float2bfloat16_rn(y)) << 16);
}
__device__ __forceinline__ void cp_async16(uint32_t dst, const void* src) {
    asm volatile("cp.async.cg.shared.global [%0], [%1], 16;" :: "r"(dst), "l"(src) : "memory");
}
// exact bf16 -> fp32 (bit shift)
__device__ __forceinline__ float bflo(uint32_t w) { return __uint_as_float(w << 16); }
__device__ __forceinline__ float bfhi(uint32_t w) { return __uint_as_float(w & 0xFFFF0000u); }

#define PADB 80   // bytes per smem tile row (64B data + 16B pad, conflict-free)

// ===========================================================================
// zero: clear accumulators each replay
// ===========================================================================
__global__ void zero_kernel(float* out, int n_out) {
    int i = blockIdx.x * blockDim.x + threadIdx.x;
    if (i < BB * SS) { g_w[i] = 0.0f; g_z[i] = 0.0f; }
    if (i < n_out)   out[i] = 0.0f;
}

// ===========================================================================
// projection: qk[B*S,512] = x @ W^T + bias, split-bf16 3-term HMMA
// (fp32-accurate). Epilogue stores bf16 q / k directly. (unchanged, passing)
// ===========================================================================
__global__ __launch_bounds__(256, 2) void proj_kernel(
    const float* __restrict__ x, const float* __restrict__ W,
    const float* __restrict__ bias)
{
    __shared__ __align__(16) char tiles[4 * 128 * PADB];

    const int tid = threadIdx.x;
    const int lane = tid & 31, wid = tid >> 5;
    const int wm = wid >> 2, wn = wid & 3;

    const float* Ab = x + (size_t)blockIdx.y * 128 * DD;
    const float* Bb = W + (size_t)blockIdx.x * 128 * DD;
    const uint32_t sb = smem_u32(tiles);

    float acc[4][4][4];
#pragma unroll
    for (int m = 0; m < 4; m++)
#pragma unroll
        for (int n = 0; n < 4; n++)
#pragma unroll
            for (int u = 0; u < 4; u++) acc[m][n][u] = 0.0f;

    const uint32_t a_row = (uint32_t)(lane & 15);
    const uint32_t a_koff = (uint32_t)((lane >> 4) << 4);
    const uint32_t b_row = (uint32_t)(lane & 7);
    const uint32_t b_koff = (uint32_t)(((lane >> 3) & 1) << 4);

    for (int kt = 0; kt < 8; kt++) {       // K = 256, BK = 32
        __syncthreads();
#pragma unroll
        for (int half = 0; half < 2; half++) {
            const float* src = half ? Bb : Ab;
            char* dh = tiles + (half ? 2 : 0) * 10240;
            char* dl = dh + 10240;
#pragma unroll
            for (int i = 0; i < 4; i++) {
                int chunk = tid + i * 256;
                int row = chunk >> 3, c4 = chunk & 7;
                float4 v = *reinterpret_cast<const float4*>(src + (size_t)row * DD + kt * 32 + c4 * 4);
                float hx = __bfloat162float(__float2bfloat16_rn(v.x));
                float hy = __bfloat162float(__float2bfloat16_rn(v.y));
                float hz = __bfloat162float(__float2bfloat16_rn(v.z));
                float hw = __bfloat162float(__float2bfloat16_rn(v.w));
                uint2 ph, pl;
                ph.x = pack_bf16(v.x, v.y); ph.y = pack_bf16(v.z, v.w);
                pl.x = pack_bf16(v.x - hx, v.y - hy); pl.y = pack_bf16(v.z - hz, v.w - hw);
                *reinterpret_cast<uint2*>(dh + row * PADB + c4 * 8) = ph;
                *reinterpret_cast<uint2*>(dl + row * PADB + c4 * 8) = pl;
            }
        }
        __syncthreads();

#pragma unroll
        for (int k16 = 0; k16 < 2; k16++) {
            const uint32_t kb = (uint32_t)(k16 * 32);
            uint32_t bh[4][2], bl[4][2];
#pragma unroll
            for (int n = 0; n < 4; n++) {
                uint32_t boff = (uint32_t)(wn * 32 + n * 8 + b_row) * PADB + kb + b_koff;
                ldmx2(bh[n], sb + 20480 + boff);
                ldmx2(bl[n], sb + 30720 + boff);
            }
#pragma unroll
            for (int m = 0; m < 4; m++) {
                uint32_t aoff = (uint32_t)(wm * 64 + m * 16 + a_row) * PADB + kb + a_koff;
                uint32_t ah[4], al[4];
                ldmx4(ah, sb + aoff);
                ldmx4(al, sb + 10240 + aoff);
#pragma unroll
                for (int n = 0; n < 4; n++) {
                    mma16816(acc[m][n], ah, bh[n]);
                    mma16816(acc[m][n], ah, bl[n]);
                    mma16816(acc[m][n], al, bh[n]);
                }
            }
        }
    }

    const int g = lane >> 2, t2 = (lane & 3) * 2;
#pragma unroll
    for (int m = 0; m < 4; m++) {
        const size_t grow = (size_t)blockIdx.y * 128 + wm * 64 + m * 16 + g;
#pragma unroll
        for (int n = 0; n < 4; n++) {
            const int col = blockIdx.x * 128 + wn * 32 + n * 8 + t2;
            const float b0 = bias[col], b1 = bias[col + 1];
            uint32_t p01 = pack_bf16(acc[m][n][0] + b0, acc[m][n][1] + b1);
            uint32_t p23 = pack_bf16(acc[m][n][2] + b0, acc[m][n][3] + b1);
            __nv_bfloat16* base = (col < DD) ? (g_q + col) : (g_k + (col - DD));
            *reinterpret_cast<uint32_t*>(base + grow * DD)       = p01;
            *reinterpret_cast<uint32_t*>(base + (grow + 8) * DD) = p23;
        }
    }
}

// ===========================================================================
// logits kernel: CTA = 128(q) x 128(k), K=256, single bf16 HMMA.
// cp.async 2-stage pipeline (BK=32). Fused epilogue: P=exp(l/16) bf16 + z.
// SMEM: 2 stages x (A|B) x 128 x 32 bf16 (PADB stride) = 40 KB.
// ===========================================================================
__global__ __launch_bounds__(256, 2) void logits_kernel() {
    __shared__ __align__(16) char tiles[2 * 2 * 128 * PADB];   // 40 KB
    __shared__ float zrow[128];

    const int tid = threadIdx.x;
    const int lane = tid & 31, wid = tid >> 5;
    const int wm = wid >> 2, wn = wid & 3;
    const int nt = blockIdx.x, qt = blockIdx.y, b = blockIdx.z;

    if (tid < 128) zrow[tid] = 0.0f;

    const uint32_t sb = smem_u32(tiles);
    const __nv_bfloat16* Qs = g_q + ((size_t)b * SS + (size_t)qt * 128) * DD;
    const __nv_bfloat16* Ks = g_k + ((size_t)b * SS + (size_t)nt * 128) * DD;

    // per-thread load coords: 4 chunks of 16B; chunks 0..511 -> A, 512..1023 -> B
    const int l_row = (tid & 511) >> 2;        // shared across i via recompute below

    float acc[4][4][4];
#pragma unroll
    for (int m = 0; m < 4; m++)
#pragma unroll
        for (int n = 0; n < 4; n++)
#pragma unroll
            for (int u = 0; u < 4; u++) acc[m][n][u] = 0.0f;

    const uint32_t a_row = (uint32_t)(lane & 15);
    const uint32_t a_koff = (uint32_t)((lane >> 4) << 4);
    const uint32_t b_row = (uint32_t)(lane & 7);
    const uint32_t b_koff = (uint32_t)(((lane >> 3) & 1) << 4);

    // stage loader: 1024 x 16B chunks -> stage s, k-tile kt
#define LOAD_STAGE(kt, s)                                                        \
    do {                                                                         \
        _Pragma("unroll")                                                        \
        for (int i = 0; i < 4; i++) {                                            \
            int chunk = tid + i * 256;                                           \
            int arr = chunk >> 9;                                                \
            int c = chunk & 511;                                                 \
            int row = c >> 2, c4 = c & 3;                                        \
            const __nv_bfloat16* src = (arr ? Ks : Qs) + (size_t)row * DD + (kt) * 32 + c4 * 8; \
            cp_async16(sb + (s) * 20480 + arr * 10240 + row * PADB + c4 * 16, src); \
        }                                                                        \
        asm volatile("cp.async.commit_group;" ::: "memory");                     \
    } while (0)

    LOAD_STAGE(0, 0);

    for (int kt = 0; kt < 8; kt++) {
        if (kt < 7) {
            LOAD_STAGE(kt + 1, (kt + 1) & 1);
            asm volatile("cp.async.wait_group 1;" ::: "memory");
        } else {
            asm volatile("cp.async.wait_group 0;" ::: "memory");
        }
        __syncthreads();

        const uint32_t st = sb + (uint32_t)(kt & 1) * 20480;
#pragma unroll
        for (int k16 = 0; k16 < 2; k16++) {
            const uint32_t kb = (uint32_t)(k16 * 32);
            uint32_t bh[4][2];
#pragma unroll
            for (int n = 0; n < 4; n++) {
                uint32_t boff = (uint32_t)(wn * 32 + n * 8 + b_row) * PADB + kb + b_koff;
                ldmx2(bh[n], st + 10240 + boff);
            }
#pragma unroll
            for (int m = 0; m < 4; m++) {
                uint32_t aoff = (uint32_t)(wm * 64 + m * 16 + a_row) * PADB + kb + a_koff;
                uint32_t ah[4];
                ldmx4(ah, st + aoff);
#pragma unroll
                for (int n = 0; n < 4; n++)
                    mma16816(acc[m][n], ah, bh[n]);
            }
        }
        __syncthreads();   // stage consumed; next cp.async may overwrite
    }
    (void)l_row;

    // ---- fused epilogue: exp, bf16 store, row sums ----
    const int g = lane >> 2, t2 = (lane & 3) * 2;
#pragma unroll
    for (int m = 0; m < 4; m++) {
        const int row_lo = wm * 64 + m * 16 + g;
        const size_t grow = (size_t)b * SS + (size_t)qt * 128 + row_lo;
        float zlo = 0.0f, zhi = 0.0f;
#pragma unroll
        for (int n = 0; n < 4; n++) {
            float e0 = __expf(acc[m][n][0] * 0.0625f);
            float e1 = __expf(acc[m][n][1] * 0.0625f);
            float e2 = __expf(acc[m][n][2] * 0.0625f);
            float e3 = __expf(acc[m][n][3] * 0.0625f);
            zlo += e0 + e1;
            zhi += e2 + e3;
            const int col = nt * 128 + wn * 32 + n * 8 + t2;
            *reinterpret_cast<uint32_t*>(g_P + grow * SS + col)       = pack_bf16(e0, e1);
            *reinterpret_cast<uint32_t*>(g_P + (grow + 8) * SS + col) = pack_bf16(e2, e3);
        }
        atomicAdd(&zrow[row_lo], zlo);
        atomicAdd(&zrow[row_lo + 8], zhi);
    }
    __syncthreads();
    if (tid < 128)
        atomicAdd(&g_z[(size_t)b * SS + (size_t)qt * 128 + tid], zrow[tid]);
}

// ===========================================================================
// column weights: w_k += sum_q P[q,k] / z_q.
// Block owns 32 q-rows (512 blocks). Thread owns 16 fixed columns ->
// REGISTER accumulators, zero smem in the loop (breaks LDS RMW chains).
// ===========================================================================
__global__ __launch_bounds__(256) void col_weights_kernel() {
    __shared__ float izs[32];
    const int tid = threadIdx.x;
    const int r0 = blockIdx.x * 32;
    const int b = r0 / SS;

    if (tid < 32) izs[tid] = 1.0f / g_z[r0 + tid];
    __syncthreads();

    float acc0[8], acc1[8];
#pragma unroll
    for (int i = 0; i < 8; i++) { acc0[i] = 0.0f; acc1[i] = 0.0f; }

    const uint4* base = reinterpret_cast<const uint4*>(g_P + (size_t)r0 * SS);
#pragma unroll 4
    for (int r = 0; r < 32; r++) {
        const float iz = izs[r];
        uint4 v0 = base[(size_t)r * 512 + tid];          // cols tid*8 .. +7
        uint4 v1 = base[(size_t)r * 512 + tid + 256];    // cols 2048 + tid*8 ..
        const uint32_t w0[4] = {v0.x, v0.y, v0.z, v0.w};
        const uint32_t w1[4] = {v1.x, v1.y, v1.z, v1.w};
#pragma unroll
        for (int h = 0; h < 4; h++) {
            acc0[2 * h]     = fmaf(bflo(w0[h]), iz, acc0[2 * h]);
            acc0[2 * h + 1] = fmaf(bfhi(w0[h]), iz, acc0[2 * h + 1]);
            acc1[2 * h]     = fmaf(bflo(w1[h]), iz, acc1[2 * h]);
            acc1[2 * h + 1] = fmaf(bfhi(w1[h]), iz, acc1[2 * h + 1]);
        }
    }

    float* wb = g_w + (size_t)b * SS;
#pragma unroll
    for (int i = 0; i < 8; i++) {
        atomicAdd(&wb[tid * 8 + i], acc0[i]);
        atomicAdd(&wb[2048 + tid * 8 + i], acc1[i]);
    }
}

// ===========================================================================
// weighted pool: out[b,d] = sum_k w[b,k] * x[b,k,d]
// ===========================================================================
__global__ void out_kernel(const float* __restrict__ x, float* __restrict__ out) {
    const int b = blockIdx.y;
    const int k0 = blockIdx.x * 64;
    const int d = threadIdx.x;

    const float* xp = x + ((size_t)b * SS + k0) * DD + d;
    const float* wp = g_w + (size_t)b * SS + k0;
    float acc = 0.0f;
#pragma unroll 8
    for (int kk = 0; kk < 64; kk++)
        acc = fmaf(wp[kk], xp[(size_t)kk * DD], acc);
    atomicAdd(&out[b * DD + d], acc);
}

// ===========================================================================
extern "C" void kernel_launch(void* const* d_in, const int* in_sizes, int n_in,
                              void* d_out, int out_size) {
    const float* x    = (const float*)d_in[0];
    const float* W    = (const float*)d_in[1];
    const float* bias = (const float*)d_in[2];
    float* out = (float*)d_out;

    // 0) zero accumulators
    zero_kernel<<<64, 256>>>(out, out_size);

    // 1) projection (split-bf16 3-term HMMA), bf16 q/k out
    {
        dim3 grid(D2 / 128, (BB * SS) / 128);
        proj_kernel<<<grid, 256>>>(x, W, bias);
    }

    // 2) logits + exp + z  (single bf16 HMMA, cp.async pipeline)
    {
        dim3 grid(SS / 128, SS / 128, BB);
        logits_kernel<<<grid, 256>>>();
    }

    // 3) column weights (register accumulation)
    col_weights_kernel<<<(BB * SS) / 32, 256>>>();

    // 4) weighted pool
    out_kernel<<<dim3(64, BB), 256>>>(x, out);
}

// round 6
// speedup vs baseline: 4.7682x; 1.1017x over previous
#include <cuda_runtime.h>
#include <cuda_bf16.h>
#include <cstdint>
#include <math.h>

#define BB 4
#define SS 4096
#define DD 256
#define D2 512

// ---- scratch (static __device__ globals; no allocation anywhere) ----
__device__ __nv_bfloat16 g_q[(size_t)BB * SS * DD];    // q bf16 (8 MB)
__device__ __nv_bfloat16 g_k[(size_t)BB * SS * DD];    // k bf16 (8 MB)
__device__ __nv_bfloat16 g_P[(size_t)BB * SS * SS];    // exp(logits) bf16 (134 MB)
__device__ float         g_z[BB * SS];                 // per-row sum-exp
__device__ float         g_w[BB * SS];                 // column weights

// ===========================================================================
// helpers
// ===========================================================================
__device__ __forceinline__ uint32_t smem_u32(const void* p) {
    uint32_t a;
    asm("{ .reg .u64 t; cvta.to.shared.u64 t, %1; cvt.u32.u64 %0, t; }" : "=r"(a) : "l"(p));
    return a;
}
__device__ __forceinline__ void ldmx4(uint32_t* r, uint32_t addr) {
    asm volatile("ldmatrix.sync.aligned.m8n8.x4.shared.b16 {%0,%1,%2,%3}, [%4];"
                 : "=r"(r[0]), "=r"(r[1]), "=r"(r[2]), "=r"(r[3]) : "r"(addr));
}
__device__ __forceinline__ void ldmx2(uint32_t* r, uint32_t addr) {
    asm volatile("ldmatrix.sync.aligned.m8n8.x2.shared.b16 {%0,%1}, [%2];"
                 : "=r"(r[0]), "=r"(r[1]) : "r"(addr));
}
__device__ __forceinline__ void mma16816(float* c, const uint32_t* a, const uint32_t* b) {
    asm volatile(
        "mma.sync.aligned.m16n8k16.row.col.f32.bf16.bf16.f32 "
        "{%0,%1,%2,%3}, {%4,%5,%6,%7}, {%8,%9}, {%0,%1,%2,%3};"
        : "+f"(c[0]), "+f"(c[1]), "+f"(c[2]), "+f"(c[3])
        : "r"(a[0]), "r"(a[1]), "r"(a[2]), "r"(a[3]), "r"(b[0]), "r"(b[1]));
}
__device__ __forceinline__ uint32_t pack_bf16(float x, float y) {
    return (uint32_t)__bfloat16_as_ushort(__float2bfloat16_rn(x))
         | ((uint32_t)__bfloat16_as_ushort(__float2bfloat16_rn(y)) << 16);
}
__device__ __forceinline__ void cp_async16(uint32_t dst, const void* src) {
    asm volatile("cp.async.cg.shared.global [%0], [%1], 16;" :: "r"(dst), "l"(src) : "memory");
}
// exact bf16 -> fp32 (bit shift)
__device__ __forceinline__ float bflo(uint32_t w) { return __uint_as_float(w << 16); }
__device__ __forceinline__ float bfhi(uint32_t w) { return __uint_as_float(w & 0xFFFF0000u); }

#define PADB 80        // bytes per smem tile row (64B data + 16B pad, conflict-free)
#define STAGE_B 20480  // one pipeline stage: 2 arrays x 128 rows x PADB
#define LG_SMEM (3 * STAGE_B)

// ===========================================================================
// zero: clear accumulators each replay
// ===========================================================================
__global__ void zero_kernel(float* out, int n_out) {
    int i = blockIdx.x * blockDim.x + threadIdx.x;
    if (i < BB * SS) { g_w[i] = 0.0f; g_z[i] = 0.0f; }
    if (i < n_out)   out[i] = 0.0f;
}

// ===========================================================================
// projection: qk[B*S,512] = x @ W^T + bias, SINGLE bf16 HMMA term.
// (q/k outputs are bf16-rounded anyway; single-term error is same order.)
// CTA 128x128, 8 warps 2x4 (warp 64x32), BK=32. SMEM: A|B = 20 KB.
// ===========================================================================
__global__ __launch_bounds__(256, 2) void proj_kernel(
    const float* __restrict__ x, const float* __restrict__ W,
    const float* __restrict__ bias)
{
    __shared__ __align__(16) char tiles[2 * 128 * PADB];

    const int tid = threadIdx.x;
    const int lane = tid & 31, wid = tid >> 5;
    const int wm = wid >> 2, wn = wid & 3;

    const float* Ab = x + (size_t)blockIdx.y * 128 * DD;
    const float* Bb = W + (size_t)blockIdx.x * 128 * DD;
    const uint32_t sb = smem_u32(tiles);

    float acc[4][4][4];
#pragma unroll
    for (int m = 0; m < 4; m++)
#pragma unroll
        for (int n = 0; n < 4; n++)
#pragma unroll
            for (int u = 0; u < 4; u++) acc[m][n][u] = 0.0f;

    const uint32_t a_row = (uint32_t)(lane & 15);
    const uint32_t a_koff = (uint32_t)((lane >> 4) << 4);
    const uint32_t b_row = (uint32_t)(lane & 7);
    const uint32_t b_koff = (uint32_t)(((lane >> 3) & 1) << 4);

    for (int kt = 0; kt < 8; kt++) {       // K = 256, BK = 32
        __syncthreads();
#pragma unroll
        for (int i = 0; i < 8; i++) {      // 2048 float4 chunks
            int chunk = tid + i * 256;
            int arr = chunk >> 10;         // 0 = A, 1 = B
            int c = chunk & 1023;
            int row = c >> 3, c4 = c & 7;
            const float* src = (arr ? Bb : Ab) + (size_t)row * DD + kt * 32 + c4 * 4;
            float4 v = *reinterpret_cast<const float4*>(src);
            uint2 p;
            p.x = pack_bf16(v.x, v.y);
            p.y = pack_bf16(v.z, v.w);
            *reinterpret_cast<uint2*>(tiles + arr * 10240 + row * PADB + c4 * 8) = p;
        }
        __syncthreads();

#pragma unroll
        for (int k16 = 0; k16 < 2; k16++) {
            const uint32_t kb = (uint32_t)(k16 * 32);
            uint32_t bh[4][2];
#pragma unroll
            for (int n = 0; n < 4; n++) {
                uint32_t boff = (uint32_t)(wn * 32 + n * 8 + b_row) * PADB + kb + b_koff;
                ldmx2(bh[n], sb + 10240 + boff);
            }
#pragma unroll
            for (int m = 0; m < 4; m++) {
                uint32_t aoff = (uint32_t)(wm * 64 + m * 16 + a_row) * PADB + kb + a_koff;
                uint32_t ah[4];
                ldmx4(ah, sb + aoff);
#pragma unroll
                for (int n = 0; n < 4; n++)
                    mma16816(acc[m][n], ah, bh[n]);
            }
        }
    }

    const int g = lane >> 2, t2 = (lane & 3) * 2;
#pragma unroll
    for (int m = 0; m < 4; m++) {
        const size_t grow = (size_t)blockIdx.y * 128 + wm * 64 + m * 16 + g;
#pragma unroll
        for (int n = 0; n < 4; n++) {
            const int col = blockIdx.x * 128 + wn * 32 + n * 8 + t2;
            const float b0 = bias[col], b1 = bias[col + 1];
            uint32_t p01 = pack_bf16(acc[m][n][0] + b0, acc[m][n][1] + b1);
            uint32_t p23 = pack_bf16(acc[m][n][2] + b0, acc[m][n][3] + b1);
            __nv_bfloat16* base = (col < DD) ? (g_q + col) : (g_k + (col - DD));
            *reinterpret_cast<uint32_t*>(base + grow * DD)       = p01;
            *reinterpret_cast<uint32_t*>(base + (grow + 8) * DD) = p23;
        }
    }
}

// ===========================================================================
// logits kernel: CTA = 128(q) x 128(k), K=256, single bf16 HMMA.
// 3-stage cp.async pipeline, ONE __syncthreads per k-iter.
// Epilogue: P=exp(l/16) bf16 staged in smem -> 16B-coalesced store; z sums.
// Dynamic SMEM: 3 x 20 KB stages (epilogue reuses first 32 KB as staging).
// ===========================================================================
__global__ __launch_bounds__(256, 2) void logits_kernel() {
    extern __shared__ __align__(16) char tiles[];
    __shared__ float zrow[128];

    const int tid = threadIdx.x;
    const int lane = tid & 31, wid = tid >> 5;
    const int wm = wid >> 2, wn = wid & 3;
    const int nt = blockIdx.x, qt = blockIdx.y, b = blockIdx.z;

    if (tid < 128) zrow[tid] = 0.0f;

    const uint32_t sb = smem_u32(tiles);
    const __nv_bfloat16* Qs = g_q + ((size_t)b * SS + (size_t)qt * 128) * DD;
    const __nv_bfloat16* Ks = g_k + ((size_t)b * SS + (size_t)nt * 128) * DD;

    float acc[4][4][4];
#pragma unroll
    for (int m = 0; m < 4; m++)
#pragma unroll
        for (int n = 0; n < 4; n++)
#pragma unroll
            for (int u = 0; u < 4; u++) acc[m][n][u] = 0.0f;

    const uint32_t a_row = (uint32_t)(lane & 15);
    const uint32_t a_koff = (uint32_t)((lane >> 4) << 4);
    const uint32_t b_row = (uint32_t)(lane & 7);
    const uint32_t b_koff = (uint32_t)(((lane >> 3) & 1) << 4);

#define LOAD_STAGE(kt, s)                                                        \
    do {                                                                         \
        _Pragma("unroll")                                                        \
        for (int i = 0; i < 4; i++) {                                            \
            int chunk = tid + i * 256;                                           \
            int arr = chunk >> 9;                                                \
            int c = chunk & 511;                                                 \
            int row = c >> 2, c4 = c & 3;                                        \
            const __nv_bfloat16* src = (arr ? Ks : Qs) + (size_t)row * DD + (kt) * 32 + c4 * 8; \
            cp_async16(sb + (uint32_t)(s) * STAGE_B + arr * 10240 + row * PADB + c4 * 16, src); \
        }                                                                        \
        asm volatile("cp.async.commit_group;" ::: "memory");                     \
    } while (0)

    LOAD_STAGE(0, 0);
    LOAD_STAGE(1, 1);

    int stage = 0;
    for (int kt = 0; kt < 8; kt++) {
        if (kt < 7) asm volatile("cp.async.wait_group 1;" ::: "memory");
        else        asm volatile("cp.async.wait_group 0;" ::: "memory");
        __syncthreads();
        if (kt + 2 < 8) {
            int ns = stage + 2; if (ns >= 3) ns -= 3;
            LOAD_STAGE(kt + 2, ns);
        }

        const uint32_t st = sb + (uint32_t)stage * STAGE_B;
#pragma unroll
        for (int k16 = 0; k16 < 2; k16++) {
            const uint32_t kb = (uint32_t)(k16 * 32);
            uint32_t bh[4][2];
#pragma unroll
            for (int n = 0; n < 4; n++) {
                uint32_t boff = (uint32_t)(wn * 32 + n * 8 + b_row) * PADB + kb + b_koff;
                ldmx2(bh[n], st + 10240 + boff);
            }
#pragma unroll
            for (int m = 0; m < 4; m++) {
                uint32_t aoff = (uint32_t)(wm * 64 + m * 16 + a_row) * PADB + kb + a_koff;
                uint32_t ah[4];
                ldmx4(ah, st + aoff);
#pragma unroll
                for (int n = 0; n < 4; n++)
                    mma16816(acc[m][n], ah, bh[n]);
            }
        }
        if (++stage == 3) stage = 0;
    }
    __syncthreads();   // mainloop reads done; smem becomes P staging

    // ---- epilogue: exp, pack to smem stage (128 x 128 bf16 = 32 KB) ----
    const int g = lane >> 2, t2 = (lane & 3) * 2;
#pragma unroll
    for (int m = 0; m < 4; m++) {
        const int row_lo = wm * 64 + m * 16 + g;
        float zlo = 0.0f, zhi = 0.0f;
#pragma unroll
        for (int n = 0; n < 4; n++) {
            float e0 = __expf(acc[m][n][0] * 0.0625f);
            float e1 = __expf(acc[m][n][1] * 0.0625f);
            float e2 = __expf(acc[m][n][2] * 0.0625f);
            float e3 = __expf(acc[m][n][3] * 0.0625f);
            zlo += e0 + e1;
            zhi += e2 + e3;
            const int col = wn * 32 + n * 8 + t2;
            *reinterpret_cast<uint32_t*>(tiles + row_lo * 256 + col * 2)       = pack_bf16(e0, e1);
            *reinterpret_cast<uint32_t*>(tiles + (row_lo + 8) * 256 + col * 2) = pack_bf16(e2, e3);
        }
        atomicAdd(&zrow[row_lo], zlo);
        atomicAdd(&zrow[row_lo + 8], zhi);
    }
    __syncthreads();

    // ---- coalesced 16B stores: 128 rows x 256 B ----
    const size_t grow0 = (size_t)b * SS + (size_t)qt * 128;
#pragma unroll
    for (int i = 0; i < 8; i++) {
        int chunk = tid + i * 256;          // 2048 chunks of 16 B
        int row = chunk >> 4, c16 = chunk & 15;
        uint4 v = *reinterpret_cast<const uint4*>(tiles + row * 256 + c16 * 16);
        *reinterpret_cast<uint4*>(g_P + (grow0 + row) * SS + nt * 128 + c16 * 8) = v;
    }
    if (tid < 128)
        atomicAdd(&g_z[grow0 + tid], zrow[tid]);
}

// ===========================================================================
// column weights: w_k += sum_q P[q,k] / z_q.  Column-partitioned:
// block = (512 q-rows) x (128 cols); 1024 blocks. Coalesced 256B row reads,
// register accumulators, smem cross-stripe reduce, 128 atomics/block.
// ===========================================================================
__global__ __launch_bounds__(256) void col_weights_kernel() {
    __shared__ float izs[512];
    __shared__ float ws[16][128];

    const int tid = threadIdx.x;
    const int r0 = blockIdx.x * 512;      // row offset within batch
    const int c0 = blockIdx.y * 128;      // col offset
    const int b  = blockIdx.z;

    for (int i = tid; i < 512; i += 256)
        izs[i] = 1.0f / g_z[(size_t)b * SS + r0 + i];
    __syncthreads();

    const int c8 = tid & 15;              // 16 chunks of 8 cols
    const int rstripe = tid >> 4;         // 16 row stripes

    float acc[8];
#pragma unroll
    for (int j = 0; j < 8; j++) acc[j] = 0.0f;

    const __nv_bfloat16* Pb = g_P + ((size_t)b * SS + r0 + rstripe) * SS + c0 + c8 * 8;
#pragma unroll 4
    for (int i = 0; i < 32; i++) {
        const float iz = izs[rstripe + i * 16];
        uint4 v = *reinterpret_cast<const uint4*>(Pb + (size_t)i * 16 * SS);
        const uint32_t w[4] = {v.x, v.y, v.z, v.w};
#pragma unroll
        for (int h = 0; h < 4; h++) {
            acc[2 * h]     = fmaf(bflo(w[h]), iz, acc[2 * h]);
            acc[2 * h + 1] = fmaf(bfhi(w[h]), iz, acc[2 * h + 1]);
        }
    }

#pragma unroll
    for (int j = 0; j < 8; j++) ws[rstripe][c8 * 8 + j] = acc[j];
    __syncthreads();

    if (tid < 128) {
        float s = 0.0f;
#pragma unroll
        for (int j = 0; j < 16; j++) s += ws[j][tid];
        atomicAdd(&g_w[(size_t)b * SS + c0 + tid], s);
    }
}

// ===========================================================================
// weighted pool: out[b,d] = sum_k w[b,k] * x[b,k,d]
// ===========================================================================
__global__ void out_kernel(const float* __restrict__ x, float* __restrict__ out) {
    const int b = blockIdx.y;
    const int k0 = blockIdx.x * 64;
    const int d = threadIdx.x;

    const float* xp = x + ((size_t)b * SS + k0) * DD + d;
    const float* wp = g_w + (size_t)b * SS + k0;
    float acc = 0.0f;
#pragma unroll 8
    for (int kk = 0; kk < 64; kk++)
        acc = fmaf(wp[kk], xp[(size_t)kk * DD], acc);
    atomicAdd(&out[b * DD + d], acc);
}

// ===========================================================================
extern "C" void kernel_launch(void* const* d_in, const int* in_sizes, int n_in,
                              void* d_out, int out_size) {
    const float* x    = (const float*)d_in[0];
    const float* W    = (const float*)d_in[1];
    const float* bias = (const float*)d_in[2];
    float* out = (float*)d_out;

    cudaFuncSetAttribute(logits_kernel, cudaFuncAttributeMaxDynamicSharedMemorySize, LG_SMEM);

    // 0) zero accumulators
    zero_kernel<<<64, 256>>>(out, out_size);

    // 1) projection (single bf16 HMMA), bf16 q/k out
    {
        dim3 grid(D2 / 128, (BB * SS) / 128);
        proj_kernel<<<grid, 256>>>(x, W, bias);
    }

    // 2) logits + exp + z  (bf16 HMMA, 3-stage cp.async, staged P store)
    {
        dim3 grid(SS / 128, SS / 128, BB);
        logits_kernel<<<grid, 256, LG_SMEM>>>();
    }

    // 3) column weights (column-partitioned, coalesced)
    {
        dim3 grid(SS / 512, SS / 128, BB);
        col_weights_kernel<<<grid, 256>>>();
    }

    // 4) weighted pool
    out_kernel<<<dim3(64, BB), 256>>>(x, out);
}